// round 2
// baseline (speedup 1.0000x reference)
#include <cuda_runtime.h>

#define HH 256
#define WW 256
#define C 64
#define O 64
#define B 16
#define NK 4
#define TILE 16
#define GROUPS 8

// ---- scratch (no allocations allowed) ----
__device__ float g_w[B * O * C * 9];        // per-batch demodulated weights
__device__ float g_sum[B * GROUPS];         // groupnorm sum
__device__ float g_sumsq[B * GROUPS];       // groupnorm sum of squares

// ============================================================================
// Kernel 0: softmax kernel selection + modulation + demodulation.
// grid (O, B), 64 threads (one per input channel i). Also zeros GN stats.
// ============================================================================
__global__ void weight_kernel(const float* __restrict__ mod,
                              const float* __restrict__ kmod,
                              const float* __restrict__ cw) {
    int o = blockIdx.x;
    int b = blockIdx.y;
    int i = threadIdx.x;  // 0..63

    // softmax over 4 kernel logits (redundant per thread, trivial cost)
    float k0 = kmod[b * NK + 0], k1 = kmod[b * NK + 1];
    float k2 = kmod[b * NK + 2], k3 = kmod[b * NK + 3];
    float m = fmaxf(fmaxf(k0, k1), fmaxf(k2, k3));
    float e0 = __expf(k0 - m), e1 = __expf(k1 - m);
    float e2 = __expf(k2 - m), e3 = __expf(k3 - m);
    float inv = 1.0f / (e0 + e1 + e2 + e3);
    float a0 = e0 * inv, a1 = e1 * inv, a2 = e2 * inv, a3 = e3 * inv;

    float mi = mod[b * C + i] + 1.0f;

    float wv[9];
    float ss = 0.0f;
#pragma unroll
    for (int k = 0; k < 9; k++) {
        int base = (o * C + i) * 9 + k;
        const int stride = O * C * 9;
        float v = a0 * cw[base] + a1 * cw[stride + base] +
                  a2 * cw[2 * stride + base] + a3 * cw[3 * stride + base];
        v *= mi;
        wv[k] = v;
        ss += v * v;
    }
    // block reduce ss over 64 threads
#pragma unroll
    for (int off = 16; off; off >>= 1)
        ss += __shfl_xor_sync(0xffffffffu, ss, off);
    __shared__ float sh[2];
    if ((i & 31) == 0) sh[i >> 5] = ss;
    __syncthreads();
    float tot = sh[0] + sh[1];
    float innorm = rsqrtf(fmaxf(tot, 1e-8f));  // clip(ss, EPS_DEMOD) then rsqrt

#pragma unroll
    for (int k = 0; k < 9; k++)
        g_w[((b * O + o) * C + i) * 9 + k] = wv[k] * innorm;

    // zero GN accumulators each launch (graph replays re-run this first)
    if (o == 0 && i < GROUPS) {
        g_sum[b * GROUPS + i] = 0.0f;
        g_sumsq[b * GROUPS + i] = 0.0f;
    }
}

// ============================================================================
// Kernel 1: per-sample 3x3 conv (SAME) + GN partial statistics.
// grid (16, 16, B): one CTA per 16x16 spatial tile of one batch element.
// 256 threads; thread = 8 consecutive px (one row half) x 8 out-channels.
// All 8 out-channels of a thread fall in one GN group -> cheap stats reduce.
// Dynamic smem: x halo tile [64][18][18] fp32 = 82944 B.
// ============================================================================
__global__ void __launch_bounds__(256, 2)
conv_kernel(const float* __restrict__ x, float* __restrict__ y) {
    extern __shared__ float xs[];  // [C][18][18]
    __shared__ float gsum[GROUPS], gsq[GROUPS];

    int b = blockIdx.z;
    int h0 = blockIdx.y * TILE;
    int w0 = blockIdx.x * TILE;
    int tid = threadIdx.x;

    if (tid < GROUPS) { gsum[tid] = 0.0f; gsq[tid] = 0.0f; }

    // ---- stage x tile with halo (zero padded) ----
    const float* xb = x + (long long)b * C * HH * WW;
    for (int idx = tid; idx < C * 18 * 18; idx += 256) {
        int ci = idx / 324;
        int rem = idx - ci * 324;
        int rr = rem / 18;
        int cc = rem - rr * 18;
        int gh = h0 + rr - 1;
        int gw = w0 + cc - 1;
        float v = 0.0f;
        if ((unsigned)gh < HH && (unsigned)gw < WW)
            v = xb[ci * (HH * WW) + gh * WW + gw];
        xs[idx] = v;
    }
    __syncthreads();

    int cg = tid & 7;          // out-channel group (== GN group index)
    int pg = tid >> 3;         // 0..31 pixel-strip id
    int r  = pg >> 1;          // output row within tile 0..15
    int c0 = (pg & 1) * 8;     // output col base within tile (0 or 8)

    float acc[8][8];           // [px][co_local]
#pragma unroll
    for (int p = 0; p < 8; p++)
#pragma unroll
        for (int q = 0; q < 8; q++) acc[p][q] = 0.0f;

    const float* wb = g_w + (long long)b * O * C * 9;

    for (int ci = 0; ci < C; ci++) {
        // x window for this thread's strip: rows r..r+2 (halo coords), cols c0..c0+9
        float xv[3][10];
#pragma unroll
        for (int tr = 0; tr < 3; tr++) {
            const float* sp = &xs[ci * 324 + (r + tr) * 18 + c0];
#pragma unroll
            for (int k = 0; k < 10; k++) xv[tr][k] = sp[k];
        }
#pragma unroll
        for (int col = 0; col < 8; col++) {
            const float* wp = wb + ((cg * 8 + col) * C + ci) * 9;
            float w0_ = wp[0], w1_ = wp[1], w2_ = wp[2];
            float w3_ = wp[3], w4_ = wp[4], w5_ = wp[5];
            float w6_ = wp[6], w7_ = wp[7], w8_ = wp[8];
#pragma unroll
            for (int px = 0; px < 8; px++) {
                float s = acc[px][col];
                s = fmaf(w0_, xv[0][px],     s);
                s = fmaf(w1_, xv[0][px + 1], s);
                s = fmaf(w2_, xv[0][px + 2], s);
                s = fmaf(w3_, xv[1][px],     s);
                s = fmaf(w4_, xv[1][px + 1], s);
                s = fmaf(w5_, xv[1][px + 2], s);
                s = fmaf(w6_, xv[2][px],     s);
                s = fmaf(w7_, xv[2][px + 1], s);
                s = fmaf(w8_, xv[2][px + 2], s);
                acc[px][col] = s;
            }
        }
    }

    // ---- store conv output (pre-norm) + local GN stats ----
    float s = 0.0f, s2 = 0.0f;
    float* yb = y + (long long)b * O * HH * WW;
    int gh = h0 + r;
    int gw = w0 + c0;
#pragma unroll
    for (int col = 0; col < 8; col++) {
        int co = cg * 8 + col;
        float4 v0 = make_float4(acc[0][col], acc[1][col], acc[2][col], acc[3][col]);
        float4 v1 = make_float4(acc[4][col], acc[5][col], acc[6][col], acc[7][col]);
        float* dst = yb + co * (HH * WW) + gh * WW + gw;
        *(float4*)dst = v0;
        *(float4*)(dst + 4) = v1;
#pragma unroll
        for (int px = 0; px < 8; px++) {
            float v = acc[px][col];
            s += v;
            s2 += v * v;
        }
    }

    // reduce over lanes sharing the same cg (lanes l, l+8, l+16, l+24)
#pragma unroll
    for (int off = 8; off < 32; off <<= 1) {
        s  += __shfl_xor_sync(0xffffffffu, s, off);
        s2 += __shfl_xor_sync(0xffffffffu, s2, off);
    }
    if ((tid & 31) < 8) {
        atomicAdd(&gsum[cg], s);
        atomicAdd(&gsq[cg], s2);
    }
    __syncthreads();
    if (tid < GROUPS) {
        atomicAdd(&g_sum[b * GROUPS + tid], gsum[tid]);
        atomicAdd(&g_sumsq[b * GROUPS + tid], gsq[tid]);
    }
}

// ============================================================================
// Kernel 2: GroupNorm finalize + SiLU, in-place on d_out, float4 vectorized.
// ============================================================================
__global__ void norm_kernel(float* __restrict__ y,
                            const float* __restrict__ gamma,
                            const float* __restrict__ beta) {
    long long i = (long long)blockIdx.x * blockDim.x + threadIdx.x;
    long long base = i * 4;
    int cidx = (int)(base >> 16);    // plane = b*64 + c (65536 floats per plane)
    int b = cidx >> 6;
    int c = cidx & 63;
    int g = c >> 3;

    const float invN = 1.0f / (8.0f * HH * WW);
    float mean = g_sum[b * GROUPS + g] * invN;
    float var = g_sumsq[b * GROUPS + g] * invN - mean * mean;
    float istd = rsqrtf(var + 1e-5f);
    float ga = gamma[c], be = beta[c];

    float4 v = *(float4*)&y[base];
    float* vp = &v.x;
#pragma unroll
    for (int k = 0; k < 4; k++) {
        float t = (vp[k] - mean) * istd * ga + be;
        vp[k] = t / (1.0f + __expf(-t));   // SiLU
    }
    *(float4*)&y[base] = v;
}

// ============================================================================
extern "C" void kernel_launch(void* const* d_in, const int* in_sizes, int n_in,
                              void* d_out, int out_size) {
    const float* x     = (const float*)d_in[0];
    const float* mod   = (const float*)d_in[1];
    const float* kmod  = (const float*)d_in[2];
    const float* cw    = (const float*)d_in[3];
    const float* gamma = (const float*)d_in[4];
    const float* beta  = (const float*)d_in[5];
    float* out = (float*)d_out;

    const int smem = C * 18 * 18 * (int)sizeof(float);  // 82944 B
    cudaFuncSetAttribute(conv_kernel,
                         cudaFuncAttributeMaxDynamicSharedMemorySize, smem);

    weight_kernel<<<dim3(O, B), 64>>>(mod, kmod, cw);
    conv_kernel<<<dim3(16, 16, B), 256, smem>>>(x, out);
    norm_kernel<<<(B * O * HH * WW / 4) / 256, 256>>>(out, gamma, beta);
}

// round 3
// speedup vs baseline: 5.0018x; 5.0018x over previous
#include <cuda_runtime.h>
#include <cstdint>

#define HH 256
#define WW 256
#define C 64
#define O 64
#define B 16
#define NK 4
#define GROUPS 8

#define XS_PLANE 328            // 18*18 = 324, padded to 328 -> conflict-free B frags
#define AS_ROW 68               // 64 padded to 68 -> conflict-free A frags
#define AS_BUF (64 * AS_ROW)    // floats per A buffer (one tap)

// ---- scratch (no allocations allowed) ----
__device__ float g_wt[B * 9 * O * C];   // tf32-rounded weights, [b][tap][o][c]
__device__ float g_sum[B * GROUPS];
__device__ float g_sumsq[B * GROUPS];

__device__ __forceinline__ float tf32r(float v) {
    uint32_t r;
    asm("cvt.rna.tf32.f32 %0, %1;" : "=r"(r) : "f"(v));
    return __uint_as_float(r);
}

__device__ __forceinline__ void mma_tf32(float* d, const uint32_t* a,
                                         uint32_t b0, uint32_t b1) {
    asm("mma.sync.aligned.m16n8k8.row.col.f32.tf32.tf32.f32 "
        "{%0,%1,%2,%3}, {%4,%5,%6,%7}, {%8,%9}, {%0,%1,%2,%3};"
        : "+f"(d[0]), "+f"(d[1]), "+f"(d[2]), "+f"(d[3])
        : "r"(a[0]), "r"(a[1]), "r"(a[2]), "r"(a[3]), "r"(b0), "r"(b1));
}

__device__ __forceinline__ void cp_async16(uint32_t dst_smem, const float* src) {
    asm volatile("cp.async.cg.shared.global [%0], [%1], 16;"
                 :: "r"(dst_smem), "l"(src));
}

// ============================================================================
// Kernel 0: softmax kernel mix + modulation + demodulation.
// Writes tf32-rounded weights in [b][tap][o][c] layout. Zeros GN accumulators.
// ============================================================================
__global__ void weight_kernel(const float* __restrict__ mod,
                              const float* __restrict__ kmod,
                              const float* __restrict__ cw) {
    int o = blockIdx.x;
    int b = blockIdx.y;
    int i = threadIdx.x;  // input channel 0..63

    float k0 = kmod[b * NK + 0], k1 = kmod[b * NK + 1];
    float k2 = kmod[b * NK + 2], k3 = kmod[b * NK + 3];
    float m = fmaxf(fmaxf(k0, k1), fmaxf(k2, k3));
    float e0 = __expf(k0 - m), e1 = __expf(k1 - m);
    float e2 = __expf(k2 - m), e3 = __expf(k3 - m);
    float inv = 1.0f / (e0 + e1 + e2 + e3);
    float a0 = e0 * inv, a1 = e1 * inv, a2 = e2 * inv, a3 = e3 * inv;

    float mi = mod[b * C + i] + 1.0f;

    float wv[9];
    float ss = 0.0f;
#pragma unroll
    for (int k = 0; k < 9; k++) {
        int base = (o * C + i) * 9 + k;
        const int stride = O * C * 9;
        float v = a0 * cw[base] + a1 * cw[stride + base] +
                  a2 * cw[2 * stride + base] + a3 * cw[3 * stride + base];
        v *= mi;
        wv[k] = v;
        ss += v * v;
    }
#pragma unroll
    for (int off = 16; off; off >>= 1)
        ss += __shfl_xor_sync(0xffffffffu, ss, off);
    __shared__ float sh[2];
    if ((i & 31) == 0) sh[i >> 5] = ss;
    __syncthreads();
    float tot = sh[0] + sh[1];
    float innorm = rsqrtf(fmaxf(tot, 1e-8f));

#pragma unroll
    for (int k = 0; k < 9; k++)
        g_wt[((b * 9 + k) * O + o) * C + i] = tf32r(wv[k] * innorm);

    if (o == 0 && i < GROUPS) {
        g_sum[b * GROUPS + i] = 0.0f;
        g_sumsq[b * GROUPS + i] = 0.0f;
    }
}

// ============================================================================
// Kernel 1: TF32 tensor-core conv (9 shifted GEMMs) + GN partial stats.
// grid (16,16,B): one CTA per 16x16 tile. 256 threads = 8 warps.
// Warp tile: M=32 out-channels (wo = wid&1) x N=64 pixels (wn = wid>>1).
// smem: xs [64][XS_PLANE] tf32 halo tile + 2 x A tap buffers [64][AS_ROW].
// ============================================================================
__global__ void __launch_bounds__(256, 1)
conv_kernel(const float* __restrict__ x, float* __restrict__ y) {
    extern __shared__ float smem[];
    float* xs = smem;                        // C * XS_PLANE
    float* as_ = smem + C * XS_PLANE;        // 2 * AS_BUF
    __shared__ float gsum[GROUPS], gsq[GROUPS];

    int b = blockIdx.z;
    int h0 = blockIdx.y * 16;
    int w0 = blockIdx.x * 16;
    int tid = threadIdx.x;
    int wid = tid >> 5, lane = tid & 31;
    int wo = wid & 1;        // O half (0/1)
    int wn = wid >> 1;       // pixel quarter (0..3): tile rows 4*wn..4*wn+3
    int g2 = lane >> 2;      // 0..7
    int qp = lane & 3;       // 0..3

    if (tid < GROUPS) { gsum[tid] = 0.0f; gsq[tid] = 0.0f; }

    const float* wtb = g_wt + (long long)b * 9 * O * C;
    uint32_t as_smem = (uint32_t)__cvta_generic_to_shared(as_);

    // prologue: start A tap0 -> buf0
    {
        const float* src = wtb;  // tap 0
#pragma unroll
        for (int j = 0; j < 4; j++) {
            int chunk = tid + j * 256;
            int o = chunk >> 4;
            int c4 = (chunk & 15) * 4;
            cp_async16(as_smem + (uint32_t)(o * AS_ROW + c4) * 4, src + o * C + c4);
        }
        asm volatile("cp.async.commit_group;");
    }

    // ---- stage x halo tile (tf32-rounded, zero-padded) ----
    const float* xb = x + (long long)b * C * HH * WW;
    for (int idx = tid; idx < C * 324; idx += 256) {
        int ci = idx / 324;
        int rem = idx - ci * 324;
        int rr = rem / 18;
        int cc = rem - rr * 18;
        int gh = h0 + rr - 1;
        int gw = w0 + cc - 1;
        float v = 0.0f;
        if ((unsigned)gh < HH && (unsigned)gw < WW)
            v = xb[ci * (HH * WW) + gh * WW + gw];
        xs[ci * XS_PLANE + rr * 18 + cc] = tf32r(v);
    }
    asm volatile("cp.async.wait_group 0;");
    __syncthreads();

    float acc[2][8][4];
#pragma unroll
    for (int mt = 0; mt < 2; mt++)
#pragma unroll
        for (int nt = 0; nt < 8; nt++)
#pragma unroll
            for (int r = 0; r < 4; r++) acc[mt][nt][r] = 0.0f;

#pragma unroll 1
    for (int tap = 0; tap < 9; tap++) {
        int buf = tap & 1;
        if (tap < 8) {
            const float* src = wtb + (tap + 1) * O * C;
            uint32_t dst = as_smem + (uint32_t)((buf ^ 1) * AS_BUF) * 4;
#pragma unroll
            for (int j = 0; j < 4; j++) {
                int chunk = tid + j * 256;
                int o = chunk >> 4;
                int c4 = (chunk & 15) * 4;
                cp_async16(dst + (uint32_t)(o * AS_ROW + c4) * 4, src + o * C + c4);
            }
            asm volatile("cp.async.commit_group;");
        }

        int kh = tap / 3;
        int kw = tap - kh * 3;
        const float* a_base = as_ + buf * AS_BUF + (wo * 32 + g2) * AS_ROW + qp;
        const float* b_base = xs + qp * XS_PLANE + (wn * 4 + kh) * 18 + kw;

#pragma unroll
        for (int kt = 0; kt < 8; kt++) {
            uint32_t a[2][4];
#pragma unroll
            for (int mt = 0; mt < 2; mt++) {
                const float* ap = a_base + mt * (16 * AS_ROW) + kt * 8;
                a[mt][0] = __float_as_uint(ap[0]);
                a[mt][1] = __float_as_uint(ap[8 * AS_ROW]);
                a[mt][2] = __float_as_uint(ap[4]);
                a[mt][3] = __float_as_uint(ap[8 * AS_ROW + 4]);
            }
            const float* bp = b_base + kt * 8 * XS_PLANE;
#pragma unroll
            for (int nt = 0; nt < 8; nt++) {
                int po = (nt >> 1) * 18 + (nt & 1) * 8 + g2;
                uint32_t b0 = __float_as_uint(bp[po]);
                uint32_t b1 = __float_as_uint(bp[4 * XS_PLANE + po]);
                mma_tf32(acc[0][nt], a[0], b0, b1);
                mma_tf32(acc[1][nt], a[1], b0, b1);
            }
        }

        if (tap < 8) asm volatile("cp.async.wait_group 0;");
        __syncthreads();
    }

    // ---- store conv output + GN partial stats ----
    float* yb = y + (long long)b * O * HH * WW;
    float s[2][2] = {{0, 0}, {0, 0}}, s2[2][2] = {{0, 0}, {0, 0}};
#pragma unroll
    for (int mt = 0; mt < 2; mt++) {
#pragma unroll
        for (int nt = 0; nt < 8; nt++) {
            int gh = h0 + wn * 4 + (nt >> 1);
            int gw = w0 + (nt & 1) * 8 + 2 * qp;
            int o_lo = wo * 32 + mt * 16 + g2;
            float c0 = acc[mt][nt][0], c1 = acc[mt][nt][1];
            float c2 = acc[mt][nt][2], c3 = acc[mt][nt][3];
            *(float2*)(yb + o_lo * (HH * WW) + gh * WW + gw) = make_float2(c0, c1);
            *(float2*)(yb + (o_lo + 8) * (HH * WW) + gh * WW + gw) = make_float2(c2, c3);
            s[mt][0] += c0 + c1;  s2[mt][0] += c0 * c0 + c1 * c1;
            s[mt][1] += c2 + c3;  s2[mt][1] += c2 * c2 + c3 * c3;
        }
    }
#pragma unroll
    for (int off = 16; off; off >>= 1) {
#pragma unroll
        for (int mt = 0; mt < 2; mt++)
#pragma unroll
            for (int hi = 0; hi < 2; hi++) {
                s[mt][hi]  += __shfl_xor_sync(0xffffffffu, s[mt][hi], off);
                s2[mt][hi] += __shfl_xor_sync(0xffffffffu, s2[mt][hi], off);
            }
    }
    if (lane == 0) {
#pragma unroll
        for (int mt = 0; mt < 2; mt++)
#pragma unroll
            for (int hi = 0; hi < 2; hi++) {
                int g = wo * 4 + mt * 2 + hi;
                atomicAdd(&gsum[g], s[mt][hi]);
                atomicAdd(&gsq[g], s2[mt][hi]);
            }
    }
    __syncthreads();
    if (tid < GROUPS) {
        atomicAdd(&g_sum[b * GROUPS + tid], gsum[tid]);
        atomicAdd(&g_sumsq[b * GROUPS + tid], gsq[tid]);
    }
}

// ============================================================================
// Kernel 2: GroupNorm finalize + SiLU, in-place, float4 vectorized.
// ============================================================================
__global__ void norm_kernel(float* __restrict__ y,
                            const float* __restrict__ gamma,
                            const float* __restrict__ beta) {
    long long i = (long long)blockIdx.x * blockDim.x + threadIdx.x;
    long long base = i * 4;
    int cidx = (int)(base >> 16);
    int b = cidx >> 6;
    int c = cidx & 63;
    int g = c >> 3;

    const float invN = 1.0f / (8.0f * HH * WW);
    float mean = g_sum[b * GROUPS + g] * invN;
    float var = g_sumsq[b * GROUPS + g] * invN - mean * mean;
    float istd = rsqrtf(var + 1e-5f);
    float ga = gamma[c], be = beta[c];

    float4 v = *(float4*)&y[base];
    float* vp = &v.x;
#pragma unroll
    for (int k = 0; k < 4; k++) {
        float t = (vp[k] - mean) * istd * ga + be;
        vp[k] = t / (1.0f + __expf(-t));
    }
    *(float4*)&y[base] = v;
}

// ============================================================================
extern "C" void kernel_launch(void* const* d_in, const int* in_sizes, int n_in,
                              void* d_out, int out_size) {
    const float* x     = (const float*)d_in[0];
    const float* mod   = (const float*)d_in[1];
    const float* kmod  = (const float*)d_in[2];
    const float* cw    = (const float*)d_in[3];
    const float* gamma = (const float*)d_in[4];
    const float* beta  = (const float*)d_in[5];
    float* out = (float*)d_out;

    const int smem = (C * XS_PLANE + 2 * AS_BUF) * (int)sizeof(float);  // 118784
    cudaFuncSetAttribute(conv_kernel,
                         cudaFuncAttributeMaxDynamicSharedMemorySize, smem);

    weight_kernel<<<dim3(O, B), 64>>>(mod, kmod, cw);
    conv_kernel<<<dim3(16, 16, B), 256, smem>>>(x, out);
    norm_kernel<<<(B * O * HH * WW / 4) / 256, 256>>>(out, gamma, beta);
}

// round 4
// speedup vs baseline: 11.3720x; 2.2736x over previous
#include <cuda_runtime.h>
#include <cuda_fp16.h>
#include <cstdint>

#define HH 256
#define WW 256
#define C 64
#define O 64
#define B 16
#define NK 4
#define GROUPS 8

#define XSP2 328                 // half2 plane stride: 18*18=324 pad->328 (==8 mod 32)
#define NPLANE2 32               // 64 channels / 2 per half2
#define A_TAP_HALVES 4096        // 2 wo * 4 kt * 2 mt * 32 lanes * 8 halves
#define A_TAP_BYTES  8192

// ---- scratch ----
__device__ __half g_wt[B * 9 * O * C];   // fp16 weights, MMA-fragment-ordered
__device__ float g_sum[B * GROUPS];
__device__ float g_sumsq[B * GROUPS];

__device__ __forceinline__ void mma_f16(float* d, const uint32_t* a,
                                        uint32_t b0, uint32_t b1) {
    asm("mma.sync.aligned.m16n8k16.row.col.f32.f16.f16.f32 "
        "{%0,%1,%2,%3}, {%4,%5,%6,%7}, {%8,%9}, {%0,%1,%2,%3};"
        : "+f"(d[0]), "+f"(d[1]), "+f"(d[2]), "+f"(d[3])
        : "r"(a[0]), "r"(a[1]), "r"(a[2]), "r"(a[3]), "r"(b0), "r"(b1));
}

__device__ __forceinline__ void cp_async16(uint32_t dst_smem, const void* src) {
    asm volatile("cp.async.cg.shared.global [%0], [%1], 16;"
                 :: "r"(dst_smem), "l"(src));
}

// ============================================================================
// Kernel 0: softmax mix + modulate + demodulate -> fp16 fragment-ordered g_wt.
// Fragment layout (halves): [b][tap][wo(2)][kt(4)][mt(2)][lane(32)][pos(8)]
//   for mma.m16n8k16 A (row-major 16x16):
//   o = wo*32+mt*16+row, c = kt*16+kk; rA = (kk>=8)*2 + (row>=8);
//   lane = (row&7)*4 + ((kk&7)>>1); pos = rA*2 + (kk&1)
// ============================================================================
__global__ void weight_kernel(const float* __restrict__ mod,
                              const float* __restrict__ kmod,
                              const float* __restrict__ cw) {
    int o = blockIdx.x;
    int b = blockIdx.y;
    int i = threadIdx.x;  // input channel 0..63

    float k0 = kmod[b * NK + 0], k1 = kmod[b * NK + 1];
    float k2 = kmod[b * NK + 2], k3 = kmod[b * NK + 3];
    float m = fmaxf(fmaxf(k0, k1), fmaxf(k2, k3));
    float e0 = __expf(k0 - m), e1 = __expf(k1 - m);
    float e2 = __expf(k2 - m), e3 = __expf(k3 - m);
    float inv = 1.0f / (e0 + e1 + e2 + e3);
    float a0 = e0 * inv, a1 = e1 * inv, a2 = e2 * inv, a3 = e3 * inv;

    float mi = mod[b * C + i] + 1.0f;

    float wv[9];
    float ss = 0.0f;
#pragma unroll
    for (int k = 0; k < 9; k++) {
        int base = (o * C + i) * 9 + k;
        const int stride = O * C * 9;
        float v = a0 * cw[base] + a1 * cw[stride + base] +
                  a2 * cw[2 * stride + base] + a3 * cw[3 * stride + base];
        v *= mi;
        wv[k] = v;
        ss += v * v;
    }
#pragma unroll
    for (int off = 16; off; off >>= 1)
        ss += __shfl_xor_sync(0xffffffffu, ss, off);
    __shared__ float sh[2];
    if ((i & 31) == 0) sh[i >> 5] = ss;
    __syncthreads();
    float tot = sh[0] + sh[1];
    float innorm = rsqrtf(fmaxf(tot, 1e-8f));

    // fragment coordinates for (o, c=i)
    int wo = o >> 5;
    int m5 = o & 31;
    int mt = m5 >> 4;
    int row = m5 & 15;
    int kt = i >> 4;
    int kk = i & 15;
    int rA = ((kk >= 8) ? 2 : 0) + ((row >= 8) ? 1 : 0);
    int lane = ((row & 7) << 2) | ((kk & 7) >> 1);
    int pos = rA * 2 + (kk & 1);

#pragma unroll
    for (int k = 0; k < 9; k++) {
        long long idx = (((((long long)(b * 9 + k) * 2 + wo) * 4 + kt) * 2 + mt)
                         * 32 + lane) * 8 + pos;
        g_wt[idx] = __float2half_rn(wv[k] * innorm);
    }

    if (o == 0 && i < GROUPS) {
        g_sum[b * GROUPS + i] = 0.0f;
        g_sumsq[b * GROUPS + i] = 0.0f;
    }
}

// ============================================================================
// Kernel 1: fp16 tensor-core conv (9 shifted GEMMs, m16n8k16) + GN stats.
// grid (16,16,B), 256 threads = 8 warps, 2 CTAs/SM.
// smem: xs2 [32 half2-planes][XSP2] channel-pair-packed halo tile (41984 B)
//       + 2 x fragment-ordered A tap buffers (16384 B)
// ============================================================================
__global__ void __launch_bounds__(256, 2)
conv_kernel(const float* __restrict__ x, float* __restrict__ y) {
    extern __shared__ char smem[];
    __half2* xs2 = (__half2*)smem;                                // 32*XSP2
    __half* as_h = (__half*)(smem + NPLANE2 * XSP2 * 4);          // 2*A_TAP_HALVES
    __shared__ float gsum[GROUPS], gsq[GROUPS];

    int b = blockIdx.z;
    int h0 = blockIdx.y * 16;
    int w0 = blockIdx.x * 16;
    int tid = threadIdx.x;
    int wid = tid >> 5, lane = tid & 31;
    int wo = wid & 1;        // O half
    int wn = wid >> 1;       // pixel quarter: tile rows 4*wn..4*wn+3
    int g2 = lane >> 2;      // 0..7
    int qp = lane & 3;       // 0..3

    if (tid < GROUPS) { gsum[tid] = 0.0f; gsq[tid] = 0.0f; }

    const __half* wtb = g_wt + (long long)b * 9 * O * C;
    uint32_t as_smem = (uint32_t)__cvta_generic_to_shared(as_h);

    // prologue: A tap0 -> buf0 (8192 B = 512 x 16B, 2 chunks/thread)
#pragma unroll
    for (int j = 0; j < 2; j++) {
        int chunk = tid + j * 256;
        cp_async16(as_smem + chunk * 16, wtb + chunk * 8);
    }
    asm volatile("cp.async.commit_group;");

    // ---- stage x halo tile as channel-pair half2 (zero padded) ----
    const float* xb = x + (long long)b * C * HH * WW;
    for (int idx = tid; idx < NPLANE2 * 324; idx += 256) {
        int ci2 = idx / 324;
        int rem = idx - ci2 * 324;
        int rr = rem / 18;
        int cc = rem - rr * 18;
        int gh = h0 + rr - 1;
        int gw = w0 + cc - 1;
        float v0 = 0.0f, v1 = 0.0f;
        if ((unsigned)gh < HH && (unsigned)gw < WW) {
            const float* p = xb + (2 * ci2) * (HH * WW) + gh * WW + gw;
            v0 = p[0];
            v1 = p[HH * WW];
        }
        xs2[ci2 * XSP2 + rr * 18 + cc] = __floats2half2_rn(v0, v1);
    }
    asm volatile("cp.async.wait_group 0;");
    __syncthreads();

    float acc[2][8][4];
#pragma unroll
    for (int mt = 0; mt < 2; mt++)
#pragma unroll
        for (int nt = 0; nt < 8; nt++)
#pragma unroll
            for (int r = 0; r < 4; r++) acc[mt][nt][r] = 0.0f;

#pragma unroll 1
    for (int tap = 0; tap < 9; tap++) {
        int buf = tap & 1;
        if (tap < 8) {
            const __half* src = wtb + (tap + 1) * (O * C);
            uint32_t dst = as_smem + (buf ^ 1) * A_TAP_BYTES;
#pragma unroll
            for (int j = 0; j < 2; j++) {
                int chunk = tid + j * 256;
                cp_async16(dst + chunk * 16, src + chunk * 8);
            }
            asm volatile("cp.async.commit_group;");
        }

        int kh = tap / 3;
        int kw = tap - kh * 3;
        // A fragments: base for this warp's wo
        const uint4* a_base = (const uint4*)(as_h + buf * A_TAP_HALVES) +
                              (wo * 4) * 2 * 32 + lane;   // + (kt*2+mt)*32
        const __half2* b_base = xs2 + qp * XSP2 + (wn * 4 + kh) * 18 + kw + g2;

#pragma unroll
        for (int kt = 0; kt < 4; kt++) {
            uint4 af0 = a_base[(kt * 2 + 0) * 32];
            uint4 af1 = a_base[(kt * 2 + 1) * 32];
            const __half2* bp = b_base + kt * 8 * XSP2;
#pragma unroll
            for (int nt = 0; nt < 8; nt++) {
                int po = (nt >> 1) * 18 + (nt & 1) * 8;
                uint32_t b0 = *(const uint32_t*)(bp + po);
                uint32_t b1 = *(const uint32_t*)(bp + 4 * XSP2 + po);
                mma_f16(acc[0][nt], (const uint32_t*)&af0, b0, b1);
                mma_f16(acc[1][nt], (const uint32_t*)&af1, b0, b1);
            }
        }

        if (tap < 8) asm volatile("cp.async.wait_group 0;");
        __syncthreads();
    }

    // ---- store conv output (fp32) + GN partial stats ----
    float* yb = y + (long long)b * O * HH * WW;
    float s[2][2] = {{0, 0}, {0, 0}}, s2[2][2] = {{0, 0}, {0, 0}};
#pragma unroll
    for (int mt = 0; mt < 2; mt++) {
#pragma unroll
        for (int nt = 0; nt < 8; nt++) {
            int gh = h0 + wn * 4 + (nt >> 1);
            int gw = w0 + (nt & 1) * 8 + 2 * qp;
            int o_lo = wo * 32 + mt * 16 + g2;
            float c0 = acc[mt][nt][0], c1 = acc[mt][nt][1];
            float c2 = acc[mt][nt][2], c3 = acc[mt][nt][3];
            *(float2*)(yb + o_lo * (HH * WW) + gh * WW + gw) = make_float2(c0, c1);
            *(float2*)(yb + (o_lo + 8) * (HH * WW) + gh * WW + gw) = make_float2(c2, c3);
            s[mt][0] += c0 + c1;  s2[mt][0] += c0 * c0 + c1 * c1;
            s[mt][1] += c2 + c3;  s2[mt][1] += c2 * c2 + c3 * c3;
        }
    }
#pragma unroll
    for (int off = 16; off; off >>= 1) {
#pragma unroll
        for (int mt = 0; mt < 2; mt++)
#pragma unroll
            for (int hi = 0; hi < 2; hi++) {
                s[mt][hi]  += __shfl_xor_sync(0xffffffffu, s[mt][hi], off);
                s2[mt][hi] += __shfl_xor_sync(0xffffffffu, s2[mt][hi], off);
            }
    }
    if (lane == 0) {
#pragma unroll
        for (int mt = 0; mt < 2; mt++)
#pragma unroll
            for (int hi = 0; hi < 2; hi++) {
                int g = wo * 4 + mt * 2 + hi;
                atomicAdd(&gsum[g], s[mt][hi]);
                atomicAdd(&gsq[g], s2[mt][hi]);
            }
    }
    __syncthreads();
    if (tid < GROUPS) {
        atomicAdd(&g_sum[b * GROUPS + tid], gsum[tid]);
        atomicAdd(&g_sumsq[b * GROUPS + tid], gsq[tid]);
    }
}

// ============================================================================
// Kernel 2: GroupNorm finalize + SiLU, in-place, float4 vectorized.
// ============================================================================
__global__ void norm_kernel(float* __restrict__ y,
                            const float* __restrict__ gamma,
                            const float* __restrict__ beta) {
    long long i = (long long)blockIdx.x * blockDim.x + threadIdx.x;
    long long base = i * 4;
    int cidx = (int)(base >> 16);
    int b = cidx >> 6;
    int c = cidx & 63;
    int g = c >> 3;

    const float invN = 1.0f / (8.0f * HH * WW);
    float mean = g_sum[b * GROUPS + g] * invN;
    float var = g_sumsq[b * GROUPS + g] * invN - mean * mean;
    float istd = rsqrtf(var + 1e-5f);
    float ga = gamma[c], be = beta[c];

    float4 v = *(float4*)&y[base];
    float* vp = &v.x;
#pragma unroll
    for (int k = 0; k < 4; k++) {
        float t = (vp[k] - mean) * istd * ga + be;
        vp[k] = t / (1.0f + __expf(-t));
    }
    *(float4*)&y[base] = v;
}

// ============================================================================
extern "C" void kernel_launch(void* const* d_in, const int* in_sizes, int n_in,
                              void* d_out, int out_size) {
    const float* x     = (const float*)d_in[0];
    const float* mod   = (const float*)d_in[1];
    const float* kmod  = (const float*)d_in[2];
    const float* cw    = (const float*)d_in[3];
    const float* gamma = (const float*)d_in[4];
    const float* beta  = (const float*)d_in[5];
    float* out = (float*)d_out;

    const int smem = NPLANE2 * XSP2 * 4 + 2 * A_TAP_BYTES;  // 41984+16384 = 58368
    cudaFuncSetAttribute(conv_kernel,
                         cudaFuncAttributeMaxDynamicSharedMemorySize, smem);

    weight_kernel<<<dim3(O, B), 64>>>(mod, kmod, cw);
    conv_kernel<<<dim3(16, 16, B), 256, smem>>>(x, out);
    norm_kernel<<<(B * O * HH * WW / 4) / 256, 256>>>(out, gamma, beta);
}